// round 13
// baseline (speedup 1.0000x reference)
#include <cuda_runtime.h>
#include <cuda_fp16.h>
#include <math.h>
#include <stdint.h>

// Problem constants
#define S_LEN 2048
#define HID   4096
#define NH    32
#define NKV   8
#define HD    128
#define ROTD  64
#define RMS_EPS 1e-6f
#define ATT_SCALE 0.08838834764831843f   // 128^-0.5
#define LOG2E     1.4426950408889634f

#define SEGQ  (S_LEN * NH * HD)
#define SEGKV (S_LEN * NKV * HD)

// ---------------------------------------------------------------------------
// Scratch
// ---------------------------------------------------------------------------
__device__ __half g_hid16[S_LEN * HID];
__device__ __half g_wq16 [NH * HD * HID];
__device__ __half g_wk16 [NKV * HD * HID];
__device__ __half g_wv16 [NKV * HD * HID];
__device__ __half g_wo16 [HID * NH * HD];

__device__ __half g_q16 [SEGQ];    // Q (normed+roped, pre-scaled ATT_SCALE*LOG2E)
__device__ __half g_k16 [SEGKV];   // K (normed+roped)
__device__ __half g_v16 [SEGKV];   // V
__device__ __half g_ao16[SEGQ];    // attention out

// ---------------------------------------------------------------------------
// Fused fp32 -> fp16 conversion, 8 elems/thread (2048 elems / block)
// ---------------------------------------------------------------------------
__global__ __launch_bounds__(256) void cvt_all(
    const float* __restrict__ s_hid, const float* __restrict__ s_wq,
    const float* __restrict__ s_wk,  const float* __restrict__ s_wv,
    const float* __restrict__ s_wo)
{
    int b = blockIdx.x;
    const float* s; __half* d; int off;
    if      (b < 4096)  { s = s_hid; d = g_hid16; off = b; }
    else if (b < 12288) { s = s_wq;  d = g_wq16;  off = b - 4096; }
    else if (b < 14336) { s = s_wk;  d = g_wk16;  off = b - 12288; }
    else if (b < 16384) { s = s_wv;  d = g_wv16;  off = b - 14336; }
    else                { s = s_wo;  d = g_wo16;  off = b - 16384; }
    size_t i = ((size_t)off * 256 + threadIdx.x) * 8;
    float4 v0 = *(const float4*)(s + i);
    float4 v1 = *(const float4*)(s + i + 4);
    __half h[8] = {__float2half_rn(v0.x), __float2half_rn(v0.y),
                   __float2half_rn(v0.z), __float2half_rn(v0.w),
                   __float2half_rn(v1.x), __float2half_rn(v1.y),
                   __float2half_rn(v1.z), __float2half_rn(v1.w)};
    *(uint4*)(d + i) = *(uint4*)h;
}

// ---------------------------------------------------------------------------
// PTX helpers
// ---------------------------------------------------------------------------
__device__ __forceinline__ void cp16(uint32_t s, const void* g) {
    asm volatile("cp.async.cg.shared.global [%0], [%1], 16;\n"
                 :: "r"(s), "l"(g) : "memory");
}
__device__ __forceinline__ void ldsm4(uint32_t& r0, uint32_t& r1,
                                      uint32_t& r2, uint32_t& r3, uint32_t a) {
    asm volatile("ldmatrix.sync.aligned.m8n8.x4.shared.b16 {%0,%1,%2,%3}, [%4];\n"
                 : "=r"(r0), "=r"(r1), "=r"(r2), "=r"(r3) : "r"(a));
}
__device__ __forceinline__ void ldsm4t(uint32_t& r0, uint32_t& r1,
                                       uint32_t& r2, uint32_t& r3, uint32_t a) {
    asm volatile("ldmatrix.sync.aligned.m8n8.x4.trans.shared.b16 {%0,%1,%2,%3}, [%4];\n"
                 : "=r"(r0), "=r"(r1), "=r"(r2), "=r"(r3) : "r"(a));
}
__device__ __forceinline__ void mma16816h(float* c, const uint32_t* a,
                                          uint32_t b0, uint32_t b1) {
    asm volatile(
        "mma.sync.aligned.m16n8k16.row.col.f32.f16.f16.f32 "
        "{%0,%1,%2,%3}, {%4,%5,%6,%7}, {%8,%9}, {%0,%1,%2,%3};\n"
        : "+f"(c[0]), "+f"(c[1]), "+f"(c[2]), "+f"(c[3])
        : "r"(a[0]), "r"(a[1]), "r"(a[2]), "r"(a[3]), "r"(b0), "r"(b1));
}
__device__ __forceinline__ uint32_t packh2(__half x, __half y) {
    __half2 t; t.x = x; t.y = y;
    return *(uint32_t*)&t;
}

// ---------------------------------------------------------------------------
// fp16 tensor-core GEMM, 128x128x64 tile, 256 threads, 3-stage, 2 CTAs/SM.
// Inner loop: B-fragment double buffer (distance-1) for LDSM/HMMA overlap.
// ---------------------------------------------------------------------------
#define FSTR    72
#define FMATB   (128u * FSTR * 2u)       // 18432 B per matrix
#define FSTAGEB (2u * FMATB)             // 36864 B per stage
#define FSTAGES 3
#define FSMEM   (FSTAGES * FSTAGEB)      // 110592 B

#define GEMM_BODY(K_)                                                          \
    const int lrow = tid >> 3;                                                 \
    const int lch  = tid & 7;                                                  \
    const int niter = (K_) / 64;                                               \
    auto issue = [&](int it) {                                                 \
        const int st = it % FSTAGES;                                           \
        const uint32_t stb = sbase + (uint32_t)st * FSTAGEB;                   \
        const int k0 = it * 64;                                                \
        _Pragma("unroll")                                                      \
        for (int i = 0; i < 4; i++) {                                          \
            const int row = i * 32 + lrow;                                     \
            const uint32_t soff = 2u * (uint32_t)(row * FSTR + lch * 8);       \
            cp16(stb + soff,          A  + (bm + row) * (K_) + k0 + lch * 8);  \
            cp16(stb + FMATB + soff,  Bp + (size_t)row * (K_) + k0 + lch * 8); \
        }                                                                      \
        asm volatile("cp.async.commit_group;\n" ::: "memory");                 \
    };                                                                         \
    float acc[2][8][4];                                                        \
    _Pragma("unroll")                                                          \
    for (int i = 0; i < 2; i++)                                                \
        _Pragma("unroll")                                                      \
        for (int j = 0; j < 8; j++)                                            \
            _Pragma("unroll")                                                  \
            for (int e = 0; e < 4; e++) acc[i][j][e] = 0.f;                    \
    issue(0); issue(1); issue(2);                                              \
    const int a_r = lane & 15;                                                 \
    const int b_r = (lane & 7) + ((lane >> 3) & 1) * 8;                        \
    const int khl = (lane >> 4) * 8;                                           \
    for (int it = 0; it < niter; ++it) {                                       \
        const int rem = niter - 1 - it;                                        \
        if (rem >= 2)      asm volatile("cp.async.wait_group 2;\n" ::: "memory"); \
        else if (rem == 1) asm volatile("cp.async.wait_group 1;\n" ::: "memory"); \
        else               asm volatile("cp.async.wait_group 0;\n" ::: "memory"); \
        __syncthreads();                                                       \
        const uint32_t sb = sbase + (uint32_t)(it % FSTAGES) * FSTAGEB;        \
        _Pragma("unroll")                                                      \
        for (int kk = 0; kk < 64; kk += 16) {                                  \
            uint32_t a[2][4];                                                  \
            _Pragma("unroll")                                                  \
            for (int mb = 0; mb < 2; mb++) {                                   \
                uint32_t addr = sb + 2u * (uint32_t)((wm + mb * 16 + a_r) * FSTR + kk + khl); \
                ldsm4(a[mb][0], a[mb][1], a[mb][2], a[mb][3], addr);           \
            }                                                                  \
            uint32_t bf[2][4];                                                 \
            {   /* prime nb=0 */                                               \
                uint32_t addr = sb + FMATB +                                   \
                    2u * (uint32_t)((wn + b_r) * FSTR + kk + khl);             \
                ldsm4(bf[0][0], bf[0][1], bf[0][2], bf[0][3], addr);           \
            }                                                                  \
            _Pragma("unroll")                                                  \
            for (int nb = 0; nb < 4; nb++) {                                   \
                if (nb < 3) {                                                  \
                    uint32_t addr = sb + FMATB +                               \
                        2u * (uint32_t)((wn + (nb + 1) * 16 + b_r) * FSTR + kk + khl); \
                    ldsm4(bf[(nb + 1) & 1][0], bf[(nb + 1) & 1][1],            \
                          bf[(nb + 1) & 1][2], bf[(nb + 1) & 1][3], addr);     \
                }                                                              \
                const uint32_t* bc = bf[nb & 1];                               \
                mma16816h(acc[0][2 * nb],     a[0], bc[0], bc[2]);             \
                mma16816h(acc[0][2 * nb + 1], a[0], bc[1], bc[3]);             \
                mma16816h(acc[1][2 * nb],     a[1], bc[0], bc[2]);             \
                mma16816h(acc[1][2 * nb + 1], a[1], bc[1], bc[3]);             \
            }                                                                  \
        }                                                                      \
        __syncthreads();                                                       \
        if (it + FSTAGES < niter) issue(it + FSTAGES);                         \
    }

// ---- fused QKV projection + RMSNorm + RoPE epilogue ----
__global__ void __launch_bounds__(256, 2) gemm_qkv(
    const __half* __restrict__ A, int K,
    const float* __restrict__ cosp, const float* __restrict__ sinp,
    const float* __restrict__ qw,   const float* __restrict__ kw)
{
    extern __shared__ __half gs[];
    const uint32_t sbase = (uint32_t)__cvta_generic_to_shared(gs);
    const int tid  = threadIdx.x;
    const int lane = tid & 31, warp = tid >> 5;
    const int wm = (warp & 3) * 32;
    const int wn = (warp >> 2) * 64;
    const size_t bm = (size_t)blockIdx.y * 128;
    const int bn = blockIdx.x * 128;

    const __half* Bp; __half* Co; int ldc, col0, mode;
    if (bn < 4096)      { Bp = g_wq16 + (size_t)bn * K;          Co = g_q16; ldc = 4096; col0 = bn;        mode = 0; }
    else if (bn < 5120) { Bp = g_wk16 + (size_t)(bn - 4096) * K; Co = g_k16; ldc = 1024; col0 = bn - 4096; mode = 1; }
    else                { Bp = g_wv16 + (size_t)(bn - 5120) * K; Co = g_v16; ldc = 1024; col0 = bn - 5120; mode = 2; }

    GEMM_BODY(K)

    if (mode != 2) {
        // ---- fused RMSNorm + RoPE on fp32 accumulators ----
        float ssq[2][2];
        #pragma unroll
        for (int mb = 0; mb < 2; mb++) {
            float s0 = 0.f, s1 = 0.f;
            #pragma unroll
            for (int n8 = 0; n8 < 8; n8++) {
                s0 += acc[mb][n8][0] * acc[mb][n8][0] + acc[mb][n8][1] * acc[mb][n8][1];
                s1 += acc[mb][n8][2] * acc[mb][n8][2] + acc[mb][n8][3] * acc[mb][n8][3];
            }
            ssq[mb][0] = s0; ssq[mb][1] = s1;
        }
        #pragma unroll
        for (int mb = 0; mb < 2; mb++)
            #pragma unroll
            for (int h2 = 0; h2 < 2; h2++) {
                ssq[mb][h2] += __shfl_xor_sync(0xffffffffu, ssq[mb][h2], 1);
                ssq[mb][h2] += __shfl_xor_sync(0xffffffffu, ssq[mb][h2], 2);
            }
        float* buf = (float*)gs;   // 256 floats (mainloop smem retired)
        if ((lane & 3) == 0) {
            #pragma unroll
            for (int mb = 0; mb < 2; mb++)
                #pragma unroll
                for (int h2 = 0; h2 < 2; h2++) {
                    int rloc = wm + mb * 16 + (lane >> 2) + h2 * 8;
                    buf[(warp >> 2) * 128 + rloc] = ssq[mb][h2];
                }
        }
        __syncthreads();
        float rs[2][2];
        #pragma unroll
        for (int mb = 0; mb < 2; mb++)
            #pragma unroll
            for (int h2 = 0; h2 < 2; h2++) {
                int rloc = wm + mb * 16 + (lane >> 2) + h2 * 8;
                float tot = buf[rloc] + buf[128 + rloc];
                rs[mb][h2] = rsqrtf(tot * (1.0f / HD) + RMS_EPS);
            }

        const float* w = (mode == 0) ? qw : kw;
        #pragma unroll
        for (int mb = 0; mb < 2; mb++) {
            #pragma unroll
            for (int n8 = 0; n8 < 8; n8++) {
                int cl = wn + n8 * 8 + (lane & 3) * 2;
                float wc0 = w[cl], wc1 = w[cl + 1];
                acc[mb][n8][0] *= rs[mb][0] * wc0;
                acc[mb][n8][1] *= rs[mb][0] * wc1;
                acc[mb][n8][2] *= rs[mb][1] * wc0;
                acc[mb][n8][3] *= rs[mb][1] * wc1;
            }
        }
        // RoPE: cols 0..63 (warps with wn==0); partner col = col ^ 32
        if (wn == 0) {
            #pragma unroll
            for (int mb = 0; mb < 2; mb++) {
                #pragma unroll
                for (int n8 = 0; n8 < 4; n8++) {
                    const int cl = n8 * 8 + (lane & 3) * 2;
                    const int ch = cl + 32;
                    #pragma unroll
                    for (int h2 = 0; h2 < 2; h2++) {
                        size_t tok = bm + wm + mb * 16 + (lane >> 2) + h2 * 8;
                        float c0 = cosp[tok * ROTD + cl],     s0 = sinp[tok * ROTD + cl];
                        float c1 = cosp[tok * ROTD + cl + 1], s1 = sinp[tok * ROTD + cl + 1];
                        float C0 = cosp[tok * ROTD + ch],     S0 = sinp[tok * ROTD + ch];
                        float C1 = cosp[tok * ROTD + ch + 1], S1 = sinp[tok * ROTD + ch + 1];
                        const int e0 = h2 * 2;
                        float alo0 = acc[mb][n8][e0],     alo1 = acc[mb][n8][e0 + 1];
                        float ahi0 = acc[mb][n8 + 4][e0], ahi1 = acc[mb][n8 + 4][e0 + 1];
                        acc[mb][n8][e0]         = alo0 * c0 - ahi0 * s0;
                        acc[mb][n8][e0 + 1]     = alo1 * c1 - ahi1 * s1;
                        acc[mb][n8 + 4][e0]     = ahi0 * C0 + alo0 * S0;
                        acc[mb][n8 + 4][e0 + 1] = ahi1 * C1 + alo1 * S1;
                    }
                }
            }
        }
        if (mode == 0) {
            const float ps = ATT_SCALE * LOG2E;
            #pragma unroll
            for (int mb = 0; mb < 2; mb++)
                #pragma unroll
                for (int n8 = 0; n8 < 8; n8++)
                    #pragma unroll
                    for (int e = 0; e < 4; e++) acc[mb][n8][e] *= ps;
        }
    }

    #pragma unroll
    for (int mb = 0; mb < 2; mb++) {
        const size_t row = bm + wm + mb * 16 + (lane >> 2);
        #pragma unroll
        for (int n8 = 0; n8 < 8; n8++) {
            const size_t col = col0 + wn + n8 * 8 + (lane & 3) * 2;
            *(uint32_t*)&Co[row * ldc + col] =
                packh2(__float2half_rn(acc[mb][n8][0]), __float2half_rn(acc[mb][n8][1]));
            *(uint32_t*)&Co[(row + 8) * ldc + col] =
                packh2(__float2half_rn(acc[mb][n8][2]), __float2half_rn(acc[mb][n8][3]));
        }
    }
}

// ---- O projection: fp32 out ----
__global__ void __launch_bounds__(256, 2) gemm_gen(
    const __half* __restrict__ A, const __half* __restrict__ B,
    float* __restrict__ C, int N, int K)
{
    extern __shared__ __half gs[];
    const uint32_t sbase = (uint32_t)__cvta_generic_to_shared(gs);
    const int tid  = threadIdx.x;
    const int lane = tid & 31, warp = tid >> 5;
    const int wm = (warp & 3) * 32;
    const int wn = (warp >> 2) * 64;
    const size_t bm = (size_t)blockIdx.y * 128;
    const int bn = blockIdx.x * 128;
    const __half* Bp = B + (size_t)bn * K;

    GEMM_BODY(K)

    #pragma unroll
    for (int mb = 0; mb < 2; mb++) {
        const size_t row = bm + wm + mb * 16 + (lane >> 2);
        #pragma unroll
        for (int n8 = 0; n8 < 8; n8++) {
            const size_t col = bn + wn + n8 * 8 + (lane & 3) * 2;
            *(float2*)&C[row * N + col] = make_float2(acc[mb][n8][0], acc[mb][n8][1]);
            *(float2*)&C[(row + 8) * N + col] = make_float2(acc[mb][n8][2], acc[mb][n8][3]);
        }
    }
}

// ---------------------------------------------------------------------------
// fp16 tensor-core causal flash attention; log2-domain softmax.
// BM=128 (8 warps x 16 rows), BN=64, D=128, 256 threads, 2 CTAs/SM.
// Fragment double-buffering in QK and PV inner loops.
// ---------------------------------------------------------------------------
#define ASTR 136
#define QMAT (128 * ASTR)
#define AMAT (64 * ASTR)
#define ATT_SMEM ((QMAT + 4 * AMAT) * 2)   // 104448 B

__global__ void __launch_bounds__(256, 2) attn_mma_kernel()
{
    extern __shared__ __half sh[];
    const uint32_t sbase = (uint32_t)__cvta_generic_to_shared(sh);

    const int tid  = threadIdx.x;
    const int lane = tid & 31, w = tid >> 5;
    const int qtile = (S_LEN / 128 - 1) - blockIdx.x;
    const int h  = blockIdx.y;
    const int hk = h >> 2;
    const int q0 = qtile * 128;
    const int qrow0 = q0 + w * 16;
    const int jmax = 2 * qtile + 1;

    const int b_r = (lane & 7) + ((lane >> 3) & 1) * 8;
    const int khl = (lane >> 4) * 8;
    const int r   = lane >> 2;

    auto load_q = [&]() {
        #pragma unroll
        for (int i = 0; i < 8; i++) {
            int c   = tid + i * 256;
            int row = c >> 4, col = c & 15;
            const __half* src = g_q16 + ((size_t)(q0 + row) * NH + h) * HD + col * 8;
            uint32_t dst = sbase + (uint32_t)(row * ASTR) * 2 + col * 16;
            cp16(dst, src);
        }
    };
    auto load_kv = [&](int j) {
        const int kvb = QMAT + (j & 1) * 2 * AMAT;
        #pragma unroll
        for (int i = 0; i < 8; i++) {
            int c   = tid + i * 256;
            int mat = c >> 10;
            int rem = c & 1023;
            int row = rem >> 4, col = rem & 15;
            const __half* srcb = (mat == 0) ? g_k16 : g_v16;
            const __half* src = srcb + ((size_t)(j * 64 + row) * NKV + hk) * HD + col * 8;
            uint32_t dst = sbase + (uint32_t)(kvb + mat * AMAT + row * ASTR) * 2 + col * 16;
            cp16(dst, src);
        }
    };

    load_q();
    load_kv(0);
    asm volatile("cp.async.commit_group;\n" ::: "memory");

    float oacc[16][4];
    #pragma unroll
    for (int i = 0; i < 16; i++)
        #pragma unroll
        for (int e = 0; e < 4; e++) oacc[i][e] = 0.f;
    float m0 = -INFINITY, m1 = -INFINITY, l0 = 0.f, l1 = 0.f;

    for (int j = 0; j <= jmax; j++) {
        // entry sync: all warps done reading buffer (j+1)&1 (last used in j-1)
        __syncthreads();
        const bool ahead = (j + 1 <= jmax);
        if (ahead) {
            load_kv(j + 1);
            asm volatile("cp.async.commit_group;\n" ::: "memory");
            asm volatile("cp.async.wait_group 1;\n" ::: "memory");
        } else {
            asm volatile("cp.async.wait_group 0;\n" ::: "memory");
        }
        __syncthreads();

        const bool active = (j * 64 <= qrow0 + 15);
        if (active) {
            const int kvb = QMAT + (j & 1) * 2 * AMAT;

            // ---- S = Q K^T (log2 units), K-fragment double buffered ----
            float sacc[8][4];
            #pragma unroll
            for (int b = 0; b < 8; b++)
                #pragma unroll
                for (int e = 0; e < 4; e++) sacc[b][e] = 0.f;

            #pragma unroll
            for (int k0 = 0; k0 < 8; k0++) {
                uint32_t qaddr = sbase +
                    (uint32_t)((w * 16 + (lane & 15)) * ASTR + k0 * 16 + 8 * (lane >> 4)) * 2;
                uint32_t aq[4];
                ldsm4(aq[0], aq[1], aq[2], aq[3], qaddr);
                uint32_t kf[2][4];
                {
                    uint32_t kaddr = sbase +
                        (uint32_t)(kvb + b_r * ASTR + k0 * 16 + khl) * 2;
                    ldsm4(kf[0][0], kf[0][1], kf[0][2], kf[0][3], kaddr);
                }
                #pragma unroll
                for (int nb = 0; nb < 4; nb++) {
                    if (nb < 3) {
                        uint32_t kaddr = sbase +
                            (uint32_t)(kvb + ((nb + 1) * 16 + b_r) * ASTR + k0 * 16 + khl) * 2;
                        ldsm4(kf[(nb + 1) & 1][0], kf[(nb + 1) & 1][1],
                              kf[(nb + 1) & 1][2], kf[(nb + 1) & 1][3], kaddr);
                    }
                    const uint32_t* kc = kf[nb & 1];
                    mma16816h(sacc[2 * nb],     aq, kc[0], kc[2]);
                    mma16816h(sacc[2 * nb + 1], aq, kc[1], kc[3]);
                }
            }

            // ---- causal mask ----
            const bool full = (j * 64 + 63 <= qrow0);
            if (!full) {
                #pragma unroll
                for (int b = 0; b < 8; b++) {
                    int colb = j * 64 + b * 8 + 2 * (lane & 3);
                    int rlo = qrow0 + r, rhi = rlo + 8;
                    if (colb     > rlo) sacc[b][0] = -1e30f;
                    if (colb + 1 > rlo) sacc[b][1] = -1e30f;
                    if (colb     > rhi) sacc[b][2] = -1e30f;
                    if (colb + 1 > rhi) sacc[b][3] = -1e30f;
                }
            }

            // ---- online softmax (log2 domain) ----
            float mx0 = -INFINITY, mx1 = -INFINITY;
            #pragma unroll
            for (int b = 0; b < 8; b++) {
                mx0 = fmaxf(mx0, fmaxf(sacc[b][0], sacc[b][1]));
                mx1 = fmaxf(mx1, fmaxf(sacc[b][2], sacc[b][3]));
            }
            mx0 = fmaxf(mx0, __shfl_xor_sync(0xffffffffu, mx0, 1));
            mx0 = fmaxf(mx0, __shfl_xor_sync(0xffffffffu, mx0, 2));
            mx1 = fmaxf(mx1, __shfl_xor_sync(0xffffffffu, mx1, 1));
            mx1 = fmaxf(mx1, __shfl_xor_sync(0xffffffffu, mx1, 2));
            float mn0 = fmaxf(m0, mx0), mn1 = fmaxf(m1, mx1);
            float f0 = exp2f(m0 - mn0), f1 = exp2f(m1 - mn1);
            m0 = mn0; m1 = mn1;

            float s0 = 0.f, s1 = 0.f;
            #pragma unroll
            for (int b = 0; b < 8; b++) {
                sacc[b][0] = exp2f(sacc[b][0] - mn0);
                sacc[b][1] = exp2f(sacc[b][1] - mn0);
                sacc[b][2] = exp2f(sacc[b][2] - mn1);
                sacc[b][3] = exp2f(sacc[b][3] - mn1);
                s0 += sacc[b][0] + sacc[b][1];
                s1 += sacc[b][2] + sacc[b][3];
            }
            s0 += __shfl_xor_sync(0xffffffffu, s0, 1);
            s0 += __shfl_xor_sync(0xffffffffu, s0, 2);
            s1 += __shfl_xor_sync(0xffffffffu, s1, 1);
            s1 += __shfl_xor_sync(0xffffffffu, s1, 2);
            l0 = l0 * f0 + s0;
            l1 = l1 * f1 + s1;

            #pragma unroll
            for (int nb = 0; nb < 16; nb++) {
                oacc[nb][0] *= f0; oacc[nb][1] *= f0;
                oacc[nb][2] *= f1; oacc[nb][3] *= f1;
            }

            // ---- pack P into fp16 A-fragments ----
            uint32_t ap[4][4];
            #pragma unroll
            for (int t = 0; t < 4; t++) {
                #pragma unroll
                for (int q = 0; q < 4; q++) {
                    const int blk = 2 * t + (q >> 1);
                    const int e0  = (q & 1) * 2;
                    ap[t][q] = packh2(__float2half_rn(sacc[blk][e0]),
                                      __float2half_rn(sacc[blk][e0 + 1]));
                }
            }

            // ---- O += P V, V-fragment double buffered ----
            #pragma unroll
            for (int t = 0; t < 4; t++) {
                uint32_t vf[2][4];
                {
                    uint32_t vaddr = sbase +
                        (uint32_t)(kvb + AMAT +
                                   (t * 16 + (lane & 15)) * ASTR + 8 * (lane >> 4)) * 2;
                    ldsm4t(vf[0][0], vf[0][1], vf[0][2], vf[0][3], vaddr);
                }
                #pragma unroll
                for (int nb = 0; nb < 8; nb++) {
                    if (nb < 7) {
                        uint32_t vaddr = sbase +
                            (uint32_t)(kvb + AMAT +
                                       (t * 16 + (lane & 15)) * ASTR + (nb + 1) * 16 + 8 * (lane >> 4)) * 2;
                        ldsm4t(vf[(nb + 1) & 1][0], vf[(nb + 1) & 1][1],
                               vf[(nb + 1) & 1][2], vf[(nb + 1) & 1][3], vaddr);
                    }
                    const uint32_t* vc = vf[nb & 1];
                    mma16816h(oacc[2 * nb],     ap[t], vc[0], vc[1]);
                    mma16816h(oacc[2 * nb + 1], ap[t], vc[2], vc[3]);
                }
            }
        }
    }

    const float inv0 = 1.f / l0, inv1 = 1.f / l1;
    #pragma unroll
    for (int nb = 0; nb < 16; nb++) {
        const int col = nb * 8 + 2 * (lane & 3);
        size_t i0 = ((size_t)(qrow0 + r) * NH + h) * HD + col;
        size_t i1 = ((size_t)(qrow0 + r + 8) * NH + h) * HD + col;
        *(uint32_t*)(g_ao16 + i0) = packh2(
            __float2half_rn(oacc[nb][0] * inv0), __float2half_rn(oacc[nb][1] * inv0));
        *(uint32_t*)(g_ao16 + i1) = packh2(
            __float2half_rn(oacc[nb][2] * inv1), __float2half_rn(oacc[nb][3] * inv1));
    }
}

// ---------------------------------------------------------------------------
// kernel_launch
// ---------------------------------------------------------------------------
extern "C" void kernel_launch(void* const* d_in, const int* in_sizes, int n_in,
                              void* d_out, int out_size)
{
    const float* hidden = (const float*)d_in[0];
    const float* cosp   = (const float*)d_in[1];
    const float* sinp   = (const float*)d_in[2];
    const float* Wq     = (const float*)d_in[3];
    const float* Wk     = (const float*)d_in[4];
    const float* Wv     = (const float*)d_in[5];
    const float* Wo     = (const float*)d_in[6];
    const float* qw     = (const float*)d_in[7];
    const float* kw     = (const float*)d_in[8];
    float* out = (float*)d_out;

    __half *hid16, *wo16, *ao16;
    cudaGetSymbolAddress((void**)&hid16, g_hid16);
    cudaGetSymbolAddress((void**)&wo16,  g_wo16);
    cudaGetSymbolAddress((void**)&ao16,  g_ao16);

    // all fp32 -> fp16 conversions, one launch
    cvt_all<<<24576, 256>>>(hidden, Wq, Wk, Wv, Wo);

    cudaFuncSetAttribute(gemm_qkv, cudaFuncAttributeMaxDynamicSharedMemorySize, FSMEM);
    cudaFuncSetAttribute(gemm_gen, cudaFuncAttributeMaxDynamicSharedMemorySize, FSMEM);

    // fused QKV projection + RMSNorm + RoPE (virtual N = 6144), fp16 out
    gemm_qkv<<<dim3(48, S_LEN / 128), 256, FSMEM>>>(hid16, HID, cosp, sinp, qw, kw);

    // fp16 causal flash attention
    cudaFuncSetAttribute(attn_mma_kernel, cudaFuncAttributeMaxDynamicSharedMemorySize, ATT_SMEM);
    attn_mma_kernel<<<dim3(S_LEN / 128, NH), 256, ATT_SMEM>>>();

    // O projection -> d_out
    gemm_gen<<<dim3(HID / 128, S_LEN / 128), 256, FSMEM>>>(
        ao16, wo16, out, HID, NH * HD);
}

// round 14
// speedup vs baseline: 1.4842x; 1.4842x over previous
#include <cuda_runtime.h>
#include <cuda_fp16.h>
#include <math.h>
#include <stdint.h>

// Problem constants
#define S_LEN 2048
#define HID   4096
#define NH    32
#define NKV   8
#define HD    128
#define ROTD  64
#define RMS_EPS 1e-6f
#define ATT_SCALE 0.08838834764831843f   // 128^-0.5
#define LOG2E     1.4426950408889634f

#define SEGQ  (S_LEN * NH * HD)
#define SEGKV (S_LEN * NKV * HD)

// ---------------------------------------------------------------------------
// Scratch
// ---------------------------------------------------------------------------
__device__ __half g_hid16[S_LEN * HID];
__device__ __half g_wq16 [NH * HD * HID];
__device__ __half g_wk16 [NKV * HD * HID];
__device__ __half g_wv16 [NKV * HD * HID];
__device__ __half g_wo16 [HID * NH * HD];

__device__ __half g_q16 [SEGQ];    // Q (normed+roped, pre-scaled ATT_SCALE*LOG2E)
__device__ __half g_k16 [SEGKV];   // K (normed+roped)
__device__ __half g_v16 [SEGKV];   // V
__device__ __half g_ao16[SEGQ];    // attention out

// ---------------------------------------------------------------------------
// Fused fp32 -> fp16 conversion, 8 elems/thread (2048 elems / block)
// ---------------------------------------------------------------------------
__global__ __launch_bounds__(256) void cvt_all(
    const float* __restrict__ s_hid, const float* __restrict__ s_wq,
    const float* __restrict__ s_wk,  const float* __restrict__ s_wv,
    const float* __restrict__ s_wo)
{
    int b = blockIdx.x;
    const float* s; __half* d; int off;
    if      (b < 4096)  { s = s_hid; d = g_hid16; off = b; }
    else if (b < 12288) { s = s_wq;  d = g_wq16;  off = b - 4096; }
    else if (b < 14336) { s = s_wk;  d = g_wk16;  off = b - 12288; }
    else if (b < 16384) { s = s_wv;  d = g_wv16;  off = b - 14336; }
    else                { s = s_wo;  d = g_wo16;  off = b - 16384; }
    size_t i = ((size_t)off * 256 + threadIdx.x) * 8;
    float4 v0 = *(const float4*)(s + i);
    float4 v1 = *(const float4*)(s + i + 4);
    __half h[8] = {__float2half_rn(v0.x), __float2half_rn(v0.y),
                   __float2half_rn(v0.z), __float2half_rn(v0.w),
                   __float2half_rn(v1.x), __float2half_rn(v1.y),
                   __float2half_rn(v1.z), __float2half_rn(v1.w)};
    *(uint4*)(d + i) = *(uint4*)h;
}

// ---------------------------------------------------------------------------
// PTX helpers
// ---------------------------------------------------------------------------
__device__ __forceinline__ void cp16(uint32_t s, const void* g) {
    asm volatile("cp.async.cg.shared.global [%0], [%1], 16;\n"
                 :: "r"(s), "l"(g) : "memory");
}
__device__ __forceinline__ void ldsm4(uint32_t& r0, uint32_t& r1,
                                      uint32_t& r2, uint32_t& r3, uint32_t a) {
    asm volatile("ldmatrix.sync.aligned.m8n8.x4.shared.b16 {%0,%1,%2,%3}, [%4];\n"
                 : "=r"(r0), "=r"(r1), "=r"(r2), "=r"(r3) : "r"(a));
}
__device__ __forceinline__ void ldsm4t(uint32_t& r0, uint32_t& r1,
                                       uint32_t& r2, uint32_t& r3, uint32_t a) {
    asm volatile("ldmatrix.sync.aligned.m8n8.x4.trans.shared.b16 {%0,%1,%2,%3}, [%4];\n"
                 : "=r"(r0), "=r"(r1), "=r"(r2), "=r"(r3) : "r"(a));
}
__device__ __forceinline__ void mma16816h(float* c, const uint32_t* a,
                                          uint32_t b0, uint32_t b1) {
    asm volatile(
        "mma.sync.aligned.m16n8k16.row.col.f32.f16.f16.f32 "
        "{%0,%1,%2,%3}, {%4,%5,%6,%7}, {%8,%9}, {%0,%1,%2,%3};\n"
        : "+f"(c[0]), "+f"(c[1]), "+f"(c[2]), "+f"(c[3])
        : "r"(a[0]), "r"(a[1]), "r"(a[2]), "r"(a[3]), "r"(b0), "r"(b1));
}
__device__ __forceinline__ uint32_t packh2(__half x, __half y) {
    __half2 t; t.x = x; t.y = y;
    return *(uint32_t*)&t;
}

// ---------------------------------------------------------------------------
// fp16 tensor-core GEMM, 128x128x64 tile, 256 threads, 3-stage, 2 CTAs/SM.
// (R8/R10/R12-proven configuration — measured best. Batched fragment loads.)
// ---------------------------------------------------------------------------
#define FSTR    72
#define FMATB   (128u * FSTR * 2u)       // 18432 B per matrix
#define FSTAGEB (2u * FMATB)             // 36864 B per stage
#define FSTAGES 3
#define FSMEM   (FSTAGES * FSTAGEB)      // 110592 B

#define GEMM_BODY(K_)                                                          \
    const int lrow = tid >> 3;                                                 \
    const int lch  = tid & 7;                                                  \
    const int niter = (K_) / 64;                                               \
    auto issue = [&](int it) {                                                 \
        const int st = it % FSTAGES;                                           \
        const uint32_t stb = sbase + (uint32_t)st * FSTAGEB;                   \
        const int k0 = it * 64;                                                \
        _Pragma("unroll")                                                      \
        for (int i = 0; i < 4; i++) {                                          \
            const int row = i * 32 + lrow;                                     \
            const uint32_t soff = 2u * (uint32_t)(row * FSTR + lch * 8);       \
            cp16(stb + soff,          A  + (bm + row) * (K_) + k0 + lch * 8);  \
            cp16(stb + FMATB + soff,  Bp + (size_t)row * (K_) + k0 + lch * 8); \
        }                                                                      \
        asm volatile("cp.async.commit_group;\n" ::: "memory");                 \
    };                                                                         \
    float acc[2][8][4];                                                        \
    _Pragma("unroll")                                                          \
    for (int i = 0; i < 2; i++)                                                \
        _Pragma("unroll")                                                      \
        for (int j = 0; j < 8; j++)                                            \
            _Pragma("unroll")                                                  \
            for (int e = 0; e < 4; e++) acc[i][j][e] = 0.f;                    \
    issue(0); issue(1); issue(2);                                              \
    const int a_r = lane & 15;                                                 \
    const int b_r = (lane & 7) + ((lane >> 3) & 1) * 8;                        \
    const int khl = (lane >> 4) * 8;                                           \
    for (int it = 0; it < niter; ++it) {                                       \
        const int rem = niter - 1 - it;                                        \
        if (rem >= 2)      asm volatile("cp.async.wait_group 2;\n" ::: "memory"); \
        else if (rem == 1) asm volatile("cp.async.wait_group 1;\n" ::: "memory"); \
        else               asm volatile("cp.async.wait_group 0;\n" ::: "memory"); \
        __syncthreads();                                                       \
        const uint32_t sb = sbase + (uint32_t)(it % FSTAGES) * FSTAGEB;        \
        _Pragma("unroll")                                                      \
        for (int kk = 0; kk < 64; kk += 16) {                                  \
            uint32_t a[2][4];                                                  \
            _Pragma("unroll")                                                  \
            for (int mb = 0; mb < 2; mb++) {                                   \
                uint32_t addr = sb + 2u * (uint32_t)((wm + mb * 16 + a_r) * FSTR + kk + khl); \
                ldsm4(a[mb][0], a[mb][1], a[mb][2], a[mb][3], addr);           \
            }                                                                  \
            uint32_t b[4][4];                                                  \
            _Pragma("unroll")                                                  \
            for (int nb = 0; nb < 4; nb++) {                                   \
                uint32_t addr = sb + FMATB +                                   \
                    2u * (uint32_t)((wn + nb * 16 + b_r) * FSTR + kk + khl);   \
                ldsm4(b[nb][0], b[nb][1], b[nb][2], b[nb][3], addr);           \
            }                                                                  \
            _Pragma("unroll")                                                  \
            for (int mb = 0; mb < 2; mb++) {                                   \
                _Pragma("unroll")                                              \
                for (int n8 = 0; n8 < 8; n8++) {                               \
                    const int nb = n8 >> 1, ww = n8 & 1;                       \
                    mma16816h(acc[mb][n8], a[mb], b[nb][ww], b[nb][ww + 2]);   \
                }                                                              \
            }                                                                  \
        }                                                                      \
        __syncthreads();                                                       \
        if (it + FSTAGES < niter) issue(it + FSTAGES);                         \
    }

// ---- fused QKV projection + RMSNorm + RoPE epilogue ----
// Virtual N = 6144 (Wq | Wk | Wv). Each 128-wide N block == one head's dims.
__global__ void __launch_bounds__(256, 2) gemm_qkv(
    const __half* __restrict__ A, int K,
    const float* __restrict__ cosp, const float* __restrict__ sinp,
    const float* __restrict__ qw,   const float* __restrict__ kw)
{
    extern __shared__ __half gs[];
    const uint32_t sbase = (uint32_t)__cvta_generic_to_shared(gs);
    const int tid  = threadIdx.x;
    const int lane = tid & 31, warp = tid >> 5;
    const int wm = (warp & 3) * 32;
    const int wn = (warp >> 2) * 64;
    const size_t bm = (size_t)blockIdx.y * 128;
    const int bn = blockIdx.x * 128;

    const __half* Bp; __half* Co; int ldc, col0, mode;
    if (bn < 4096)      { Bp = g_wq16 + (size_t)bn * K;          Co = g_q16; ldc = 4096; col0 = bn;        mode = 0; }
    else if (bn < 5120) { Bp = g_wk16 + (size_t)(bn - 4096) * K; Co = g_k16; ldc = 1024; col0 = bn - 4096; mode = 1; }
    else                { Bp = g_wv16 + (size_t)(bn - 5120) * K; Co = g_v16; ldc = 1024; col0 = bn - 5120; mode = 2; }

    GEMM_BODY(K)

    if (mode != 2) {
        // ---- fused RMSNorm + RoPE on fp32 accumulators ----
        float ssq[2][2];
        #pragma unroll
        for (int mb = 0; mb < 2; mb++) {
            float s0 = 0.f, s1 = 0.f;
            #pragma unroll
            for (int n8 = 0; n8 < 8; n8++) {
                s0 += acc[mb][n8][0] * acc[mb][n8][0] + acc[mb][n8][1] * acc[mb][n8][1];
                s1 += acc[mb][n8][2] * acc[mb][n8][2] + acc[mb][n8][3] * acc[mb][n8][3];
            }
            ssq[mb][0] = s0; ssq[mb][1] = s1;
        }
        #pragma unroll
        for (int mb = 0; mb < 2; mb++)
            #pragma unroll
            for (int h2 = 0; h2 < 2; h2++) {
                ssq[mb][h2] += __shfl_xor_sync(0xffffffffu, ssq[mb][h2], 1);
                ssq[mb][h2] += __shfl_xor_sync(0xffffffffu, ssq[mb][h2], 2);
            }
        // cross-warp (wn=0 vs wn=64 partials) via smem (mainloop smem retired)
        float* buf = (float*)gs;   // 256 floats
        if ((lane & 3) == 0) {
            #pragma unroll
            for (int mb = 0; mb < 2; mb++)
                #pragma unroll
                for (int h2 = 0; h2 < 2; h2++) {
                    int rloc = wm + mb * 16 + (lane >> 2) + h2 * 8;
                    buf[(warp >> 2) * 128 + rloc] = ssq[mb][h2];
                }
        }
        __syncthreads();
        float rs[2][2];
        #pragma unroll
        for (int mb = 0; mb < 2; mb++)
            #pragma unroll
            for (int h2 = 0; h2 < 2; h2++) {
                int rloc = wm + mb * 16 + (lane >> 2) + h2 * 8;
                float tot = buf[rloc] + buf[128 + rloc];
                rs[mb][h2] = rsqrtf(tot * (1.0f / HD) + RMS_EPS);
            }

        const float* w = (mode == 0) ? qw : kw;
        // normalize (x * rs * w[d])
        #pragma unroll
        for (int mb = 0; mb < 2; mb++) {
            #pragma unroll
            for (int n8 = 0; n8 < 8; n8++) {
                int cl = wn + n8 * 8 + (lane & 3) * 2;   // 0..127 within head
                float wc0 = w[cl], wc1 = w[cl + 1];
                acc[mb][n8][0] *= rs[mb][0] * wc0;
                acc[mb][n8][1] *= rs[mb][0] * wc1;
                acc[mb][n8][2] *= rs[mb][1] * wc0;
                acc[mb][n8][3] *= rs[mb][1] * wc1;
            }
        }
        // RoPE: only cols 0..63 (warps with wn==0); partner col = col ^ 32
        if (wn == 0) {
            #pragma unroll
            for (int mb = 0; mb < 2; mb++) {
                #pragma unroll
                for (int n8 = 0; n8 < 4; n8++) {
                    const int cl = n8 * 8 + (lane & 3) * 2;   // 0..30
                    const int ch = cl + 32;
                    #pragma unroll
                    for (int h2 = 0; h2 < 2; h2++) {
                        size_t tok = bm + wm + mb * 16 + (lane >> 2) + h2 * 8;
                        float c0 = cosp[tok * ROTD + cl],     s0 = sinp[tok * ROTD + cl];
                        float c1 = cosp[tok * ROTD + cl + 1], s1 = sinp[tok * ROTD + cl + 1];
                        float C0 = cosp[tok * ROTD + ch],     S0 = sinp[tok * ROTD + ch];
                        float C1 = cosp[tok * ROTD + ch + 1], S1 = sinp[tok * ROTD + ch + 1];
                        const int e0 = h2 * 2;
                        float alo0 = acc[mb][n8][e0],     alo1 = acc[mb][n8][e0 + 1];
                        float ahi0 = acc[mb][n8 + 4][e0], ahi1 = acc[mb][n8 + 4][e0 + 1];
                        acc[mb][n8][e0]         = alo0 * c0 - ahi0 * s0;
                        acc[mb][n8][e0 + 1]     = alo1 * c1 - ahi1 * s1;
                        acc[mb][n8 + 4][e0]     = ahi0 * C0 + alo0 * S0;
                        acc[mb][n8 + 4][e0 + 1] = ahi1 * C1 + alo1 * S1;
                    }
                }
            }
        }
        // Q pre-scale for log2-domain softmax
        if (mode == 0) {
            const float ps = ATT_SCALE * LOG2E;
            #pragma unroll
            for (int mb = 0; mb < 2; mb++)
                #pragma unroll
                for (int n8 = 0; n8 < 8; n8++)
                    #pragma unroll
                    for (int e = 0; e < 4; e++) acc[mb][n8][e] *= ps;
        }
    }

    #pragma unroll
    for (int mb = 0; mb < 2; mb++) {
        const size_t row = bm + wm + mb * 16 + (lane >> 2);
        #pragma unroll
        for (int n8 = 0; n8 < 8; n8++) {
            const size_t col = col0 + wn + n8 * 8 + (lane & 3) * 2;
            *(uint32_t*)&Co[row * ldc + col] =
                packh2(__float2half_rn(acc[mb][n8][0]), __float2half_rn(acc[mb][n8][1]));
            *(uint32_t*)&Co[(row + 8) * ldc + col] =
                packh2(__float2half_rn(acc[mb][n8][2]), __float2half_rn(acc[mb][n8][3]));
        }
    }
}

// ---- O projection: fp32 out ----
__global__ void __launch_bounds__(256, 2) gemm_gen(
    const __half* __restrict__ A, const __half* __restrict__ B,
    float* __restrict__ C, int N, int K)
{
    extern __shared__ __half gs[];
    const uint32_t sbase = (uint32_t)__cvta_generic_to_shared(gs);
    const int tid  = threadIdx.x;
    const int lane = tid & 31, warp = tid >> 5;
    const int wm = (warp & 3) * 32;
    const int wn = (warp >> 2) * 64;
    const size_t bm = (size_t)blockIdx.y * 128;
    const int bn = blockIdx.x * 128;
    const __half* Bp = B + (size_t)bn * K;

    GEMM_BODY(K)

    #pragma unroll
    for (int mb = 0; mb < 2; mb++) {
        const size_t row = bm + wm + mb * 16 + (lane >> 2);
        #pragma unroll
        for (int n8 = 0; n8 < 8; n8++) {
            const size_t col = bn + wn + n8 * 8 + (lane & 3) * 2;
            *(float2*)&C[row * N + col] = make_float2(acc[mb][n8][0], acc[mb][n8][1]);
            *(float2*)&C[(row + 8) * N + col] = make_float2(acc[mb][n8][2], acc[mb][n8][3]);
        }
    }
}

// ---------------------------------------------------------------------------
// fp16 tensor-core causal flash attention; log2-domain softmax.
// BM=128 (8 warps x 16 rows), BN=64, D=128, 256 threads, 2 CTAs/SM.
// R10 loop structure + entry sync (closes buffer-rotation race).
// ---------------------------------------------------------------------------
#define ASTR 136
#define QMAT (128 * ASTR)
#define AMAT (64 * ASTR)
#define ATT_SMEM ((QMAT + 4 * AMAT) * 2)   // 104448 B

__global__ void __launch_bounds__(256, 2) attn_mma_kernel()
{
    extern __shared__ __half sh[];
    const uint32_t sbase = (uint32_t)__cvta_generic_to_shared(sh);

    const int tid  = threadIdx.x;
    const int lane = tid & 31, w = tid >> 5;
    const int qtile = (S_LEN / 128 - 1) - blockIdx.x;
    const int h  = blockIdx.y;
    const int hk = h >> 2;
    const int q0 = qtile * 128;
    const int qrow0 = q0 + w * 16;
    const int jmax = 2 * qtile + 1;

    const int b_r = (lane & 7) + ((lane >> 3) & 1) * 8;
    const int khl = (lane >> 4) * 8;
    const int r   = lane >> 2;

    auto load_q = [&]() {
        #pragma unroll
        for (int i = 0; i < 8; i++) {
            int c   = tid + i * 256;
            int row = c >> 4, col = c & 15;
            const __half* src = g_q16 + ((size_t)(q0 + row) * NH + h) * HD + col * 8;
            uint32_t dst = sbase + (uint32_t)(row * ASTR) * 2 + col * 16;
            cp16(dst, src);
        }
    };
    auto load_kv = [&](int j) {
        const int kvb = QMAT + (j & 1) * 2 * AMAT;
        #pragma unroll
        for (int i = 0; i < 8; i++) {
            int c   = tid + i * 256;
            int mat = c >> 10;
            int rem = c & 1023;
            int row = rem >> 4, col = rem & 15;
            const __half* srcb = (mat == 0) ? g_k16 : g_v16;
            const __half* src = srcb + ((size_t)(j * 64 + row) * NKV + hk) * HD + col * 8;
            uint32_t dst = sbase + (uint32_t)(kvb + mat * AMAT + row * ASTR) * 2 + col * 16;
            cp16(dst, src);
        }
    };

    load_q();
    load_kv(0);
    asm volatile("cp.async.commit_group;\n" ::: "memory");

    float oacc[16][4];
    #pragma unroll
    for (int i = 0; i < 16; i++)
        #pragma unroll
        for (int e = 0; e < 4; e++) oacc[i][e] = 0.f;
    float m0 = -INFINITY, m1 = -INFINITY, l0 = 0.f, l1 = 0.f;

    for (int j = 0; j <= jmax; j++) {
        // entry sync: all warps done reading buffer (j+1)&1 (last used in j-1)
        __syncthreads();
        const bool ahead = (j + 1 <= jmax);
        if (ahead) {
            load_kv(j + 1);
            asm volatile("cp.async.commit_group;\n" ::: "memory");
            asm volatile("cp.async.wait_group 1;\n" ::: "memory");
        } else {
            asm volatile("cp.async.wait_group 0;\n" ::: "memory");
        }
        __syncthreads();

        const bool active = (j * 64 <= qrow0 + 15);
        if (active) {
            const int kvb = QMAT + (j & 1) * 2 * AMAT;

            // ---- S = Q K^T (log2 units; Q pre-scaled) ----
            float sacc[8][4];
            #pragma unroll
            for (int b = 0; b < 8; b++)
                #pragma unroll
                for (int e = 0; e < 4; e++) sacc[b][e] = 0.f;

            #pragma unroll
            for (int k0 = 0; k0 < 8; k0++) {
                uint32_t qaddr = sbase +
                    (uint32_t)((w * 16 + (lane & 15)) * ASTR + k0 * 16 + 8 * (lane >> 4)) * 2;
                uint32_t aq[4];
                ldsm4(aq[0], aq[1], aq[2], aq[3], qaddr);
                #pragma unroll
                for (int nb = 0; nb < 4; nb++) {
                    uint32_t kaddr = sbase +
                        (uint32_t)(kvb + (nb * 16 + b_r) * ASTR + k0 * 16 + khl) * 2;
                    uint32_t kf[4];
                    ldsm4(kf[0], kf[1], kf[2], kf[3], kaddr);
                    mma16816h(sacc[2 * nb],     aq, kf[0], kf[2]);
                    mma16816h(sacc[2 * nb + 1], aq, kf[1], kf[3]);
                }
            }

            // ---- causal mask ----
            const bool full = (j * 64 + 63 <= qrow0);
            if (!full) {
                #pragma unroll
                for (int b = 0; b < 8; b++) {
                    int colb = j * 64 + b * 8 + 2 * (lane & 3);
                    int rlo = qrow0 + r, rhi = rlo + 8;
                    if (colb     > rlo) sacc[b][0] = -1e30f;
                    if (colb + 1 > rlo) sacc[b][1] = -1e30f;
                    if (colb     > rhi) sacc[b][2] = -1e30f;
                    if (colb + 1 > rhi) sacc[b][3] = -1e30f;
                }
            }

            // ---- online softmax (log2 domain) ----
            float mx0 = -INFINITY, mx1 = -INFINITY;
            #pragma unroll
            for (int b = 0; b < 8; b++) {
                mx0 = fmaxf(mx0, fmaxf(sacc[b][0], sacc[b][1]));
                mx1 = fmaxf(mx1, fmaxf(sacc[b][2], sacc[b][3]));
            }
            mx0 = fmaxf(mx0, __shfl_xor_sync(0xffffffffu, mx0, 1));
            mx0 = fmaxf(mx0, __shfl_xor_sync(0xffffffffu, mx0, 2));
            mx1 = fmaxf(mx1, __shfl_xor_sync(0xffffffffu, mx1, 1));
            mx1 = fmaxf(mx1, __shfl_xor_sync(0xffffffffu, mx1, 2));
            float mn0 = fmaxf(m0, mx0), mn1 = fmaxf(m1, mx1);
            float f0 = exp2f(m0 - mn0), f1 = exp2f(m1 - mn1);
            m0 = mn0; m1 = mn1;

            float s0 = 0.f, s1 = 0.f;
            #pragma unroll
            for (int b = 0; b < 8; b++) {
                sacc[b][0] = exp2f(sacc[b][0] - mn0);
                sacc[b][1] = exp2f(sacc[b][1] - mn0);
                sacc[b][2] = exp2f(sacc[b][2] - mn1);
                sacc[b][3] = exp2f(sacc[b][3] - mn1);
                s0 += sacc[b][0] + sacc[b][1];
                s1 += sacc[b][2] + sacc[b][3];
            }
            s0 += __shfl_xor_sync(0xffffffffu, s0, 1);
            s0 += __shfl_xor_sync(0xffffffffu, s0, 2);
            s1 += __shfl_xor_sync(0xffffffffu, s1, 1);
            s1 += __shfl_xor_sync(0xffffffffu, s1, 2);
            l0 = l0 * f0 + s0;
            l1 = l1 * f1 + s1;

            #pragma unroll
            for (int nb = 0; nb < 16; nb++) {
                oacc[nb][0] *= f0; oacc[nb][1] *= f0;
                oacc[nb][2] *= f1; oacc[nb][3] *= f1;
            }

            // ---- pack P into fp16 A-fragments ----
            uint32_t ap[4][4];
            #pragma unroll
            for (int t = 0; t < 4; t++) {
                #pragma unroll
                for (int q = 0; q < 4; q++) {
                    const int blk = 2 * t + (q >> 1);
                    const int e0  = (q & 1) * 2;
                    ap[t][q] = packh2(__float2half_rn(sacc[blk][e0]),
                                      __float2half_rn(sacc[blk][e0 + 1]));
                }
            }

            // ---- O += P V ----
            #pragma unroll
            for (int t = 0; t < 4; t++) {
                #pragma unroll
                for (int nb = 0; nb < 8; nb++) {
                    uint32_t vaddr = sbase +
                        (uint32_t)(kvb + AMAT +
                                   (t * 16 + (lane & 15)) * ASTR + nb * 16 + 8 * (lane >> 4)) * 2;
                    uint32_t vf[4];
                    ldsm4t(vf[0], vf[1], vf[2], vf[3], vaddr);
                    mma16816h(oacc[2 * nb],     ap[t], vf[0], vf[1]);
                    mma16816h(oacc[2 * nb + 1], ap[t], vf[2], vf[3]);
                }
            }
        }
    }

    const float inv0 = 1.f / l0, inv1 = 1.f / l1;
    #pragma unroll
    for (int nb = 0; nb < 16; nb++) {
        const int col = nb * 8 + 2 * (lane & 3);
        size_t i0 = ((size_t)(qrow0 + r) * NH + h) * HD + col;
        size_t i1 = ((size_t)(qrow0 + r + 8) * NH + h) * HD + col;
        *(uint32_t*)(g_ao16 + i0) = packh2(
            __float2half_rn(oacc[nb][0] * inv0), __float2half_rn(oacc[nb][1] * inv0));
        *(uint32_t*)(g_ao16 + i1) = packh2(
            __float2half_rn(oacc[nb][2] * inv1), __float2half_rn(oacc[nb][3] * inv1));
    }
}

// ---------------------------------------------------------------------------
// kernel_launch
// ---------------------------------------------------------------------------
extern "C" void kernel_launch(void* const* d_in, const int* in_sizes, int n_in,
                              void* d_out, int out_size)
{
    const float* hidden = (const float*)d_in[0];
    const float* cosp   = (const float*)d_in[1];
    const float* sinp   = (const float*)d_in[2];
    const float* Wq     = (const float*)d_in[3];
    const float* Wk     = (const float*)d_in[4];
    const float* Wv     = (const float*)d_in[5];
    const float* Wo     = (const float*)d_in[6];
    const float* qw     = (const float*)d_in[7];
    const float* kw     = (const float*)d_in[8];
    float* out = (float*)d_out;

    __half *hid16, *wo16, *ao16;
    cudaGetSymbolAddress((void**)&hid16, g_hid16);
    cudaGetSymbolAddress((void**)&wo16,  g_wo16);
    cudaGetSymbolAddress((void**)&ao16,  g_ao16);

    // all fp32 -> fp16 conversions, one launch
    cvt_all<<<24576, 256>>>(hidden, Wq, Wk, Wv, Wo);

    cudaFuncSetAttribute(gemm_qkv, cudaFuncAttributeMaxDynamicSharedMemorySize, FSMEM);
    cudaFuncSetAttribute(gemm_gen, cudaFuncAttributeMaxDynamicSharedMemorySize, FSMEM);

    // fused QKV projection + RMSNorm + RoPE (virtual N = 6144), fp16 out
    gemm_qkv<<<dim3(48, S_LEN / 128), 256, FSMEM>>>(hid16, HID, cosp, sinp, qw, kw);

    // fp16 causal flash attention
    cudaFuncSetAttribute(attn_mma_kernel, cudaFuncAttributeMaxDynamicSharedMemorySize, ATT_SMEM);
    attn_mma_kernel<<<dim3(S_LEN / 128, NH), 256, ATT_SMEM>>>();

    // O projection -> d_out
    gemm_gen<<<dim3(HID / 128, S_LEN / 128), 256, FSMEM>>>(
        ao16, wo16, out, HID, NH * HD);
}

// round 15
// speedup vs baseline: 1.5190x; 1.0234x over previous
#include <cuda_runtime.h>
#include <cuda_fp16.h>
#include <math.h>
#include <stdint.h>

// Problem constants
#define S_LEN 2048
#define HID   4096
#define NH    32
#define NKV   8
#define HD    128
#define ROTD  64
#define RMS_EPS 1e-6f
#define ATT_SCALE 0.08838834764831843f   // 128^-0.5
#define LOG2E     1.4426950408889634f

#define SEGQ  (S_LEN * NH * HD)
#define SEGKV (S_LEN * NKV * HD)

// ---------------------------------------------------------------------------
// Scratch
// ---------------------------------------------------------------------------
__device__ __half g_hid16[S_LEN * HID];
__device__ __half g_wq16 [NH * HD * HID];
__device__ __half g_wk16 [NKV * HD * HID];
__device__ __half g_wv16 [NKV * HD * HID];
__device__ __half g_wo16 [HID * NH * HD];

__device__ __half g_q16 [SEGQ];    // Q (normed+roped, pre-scaled ATT_SCALE*LOG2E)
__device__ __half g_k16 [SEGKV];   // K (normed+roped)
__device__ __half g_v16 [SEGKV];   // V
__device__ __half g_ao16[SEGQ];    // attention out

// ---------------------------------------------------------------------------
// Fused fp32 -> fp16 conversion, 8 elems/thread (2048 elems / block)
// ---------------------------------------------------------------------------
__global__ __launch_bounds__(256) void cvt_all(
    const float* __restrict__ s_hid, const float* __restrict__ s_wq,
    const float* __restrict__ s_wk,  const float* __restrict__ s_wv,
    const float* __restrict__ s_wo)
{
    int b = blockIdx.x;
    const float* s; __half* d; int off;
    if      (b < 4096)  { s = s_hid; d = g_hid16; off = b; }
    else if (b < 12288) { s = s_wq;  d = g_wq16;  off = b - 4096; }
    else if (b < 14336) { s = s_wk;  d = g_wk16;  off = b - 12288; }
    else if (b < 16384) { s = s_wv;  d = g_wv16;  off = b - 14336; }
    else                { s = s_wo;  d = g_wo16;  off = b - 16384; }
    size_t i = ((size_t)off * 256 + threadIdx.x) * 8;
    float4 v0 = *(const float4*)(s + i);
    float4 v1 = *(const float4*)(s + i + 4);
    __half h[8] = {__float2half_rn(v0.x), __float2half_rn(v0.y),
                   __float2half_rn(v0.z), __float2half_rn(v0.w),
                   __float2half_rn(v1.x), __float2half_rn(v1.y),
                   __float2half_rn(v1.z), __float2half_rn(v1.w)};
    *(uint4*)(d + i) = *(uint4*)h;
}

// ---------------------------------------------------------------------------
// PTX helpers
// ---------------------------------------------------------------------------
__device__ __forceinline__ void cp16(uint32_t s, const void* g) {
    asm volatile("cp.async.cg.shared.global [%0], [%1], 16;\n"
                 :: "r"(s), "l"(g) : "memory");
}
__device__ __forceinline__ void ldsm4(uint32_t& r0, uint32_t& r1,
                                      uint32_t& r2, uint32_t& r3, uint32_t a) {
    asm volatile("ldmatrix.sync.aligned.m8n8.x4.shared.b16 {%0,%1,%2,%3}, [%4];\n"
                 : "=r"(r0), "=r"(r1), "=r"(r2), "=r"(r3) : "r"(a));
}
__device__ __forceinline__ void ldsm4t(uint32_t& r0, uint32_t& r1,
                                       uint32_t& r2, uint32_t& r3, uint32_t a) {
    asm volatile("ldmatrix.sync.aligned.m8n8.x4.trans.shared.b16 {%0,%1,%2,%3}, [%4];\n"
                 : "=r"(r0), "=r"(r1), "=r"(r2), "=r"(r3) : "r"(a));
}
__device__ __forceinline__ void mma16816h(float* c, const uint32_t* a,
                                          uint32_t b0, uint32_t b1) {
    asm volatile(
        "mma.sync.aligned.m16n8k16.row.col.f32.f16.f16.f32 "
        "{%0,%1,%2,%3}, {%4,%5,%6,%7}, {%8,%9}, {%0,%1,%2,%3};\n"
        : "+f"(c[0]), "+f"(c[1]), "+f"(c[2]), "+f"(c[3])
        : "r"(a[0]), "r"(a[1]), "r"(a[2]), "r"(a[3]), "r"(b0), "r"(b1));
}
__device__ __forceinline__ uint32_t packh2(__half x, __half y) {
    __half2 t; t.x = x; t.y = y;
    return *(uint32_t*)&t;
}

// ---------------------------------------------------------------------------
// fp16 tensor-core GEMM, 128x128x64 tile, 256 threads, 3-stage, 2 CTAs/SM.
// (R8/R10/R12-proven configuration — measured best. Batched fragment loads.)
// ---------------------------------------------------------------------------
#define FSTR    72
#define FMATB   (128u * FSTR * 2u)       // 18432 B per matrix
#define FSTAGEB (2u * FMATB)             // 36864 B per stage
#define FSTAGES 3
#define FSMEM   (FSTAGES * FSTAGEB)      // 110592 B

#define GEMM_BODY(K_)                                                          \
    const int lrow = tid >> 3;                                                 \
    const int lch  = tid & 7;                                                  \
    const int niter = (K_) / 64;                                               \
    auto issue = [&](int it) {                                                 \
        const int st = it % FSTAGES;                                           \
        const uint32_t stb = sbase + (uint32_t)st * FSTAGEB;                   \
        const int k0 = it * 64;                                                \
        _Pragma("unroll")                                                      \
        for (int i = 0; i < 4; i++) {                                          \
            const int row = i * 32 + lrow;                                     \
            const uint32_t soff = 2u * (uint32_t)(row * FSTR + lch * 8);       \
            cp16(stb + soff,          A  + (bm + row) * (K_) + k0 + lch * 8);  \
            cp16(stb + FMATB + soff,  Bp + (size_t)row * (K_) + k0 + lch * 8); \
        }                                                                      \
        asm volatile("cp.async.commit_group;\n" ::: "memory");                 \
    };                                                                         \
    float acc[2][8][4];                                                        \
    _Pragma("unroll")                                                          \
    for (int i = 0; i < 2; i++)                                                \
        _Pragma("unroll")                                                      \
        for (int j = 0; j < 8; j++)                                            \
            _Pragma("unroll")                                                  \
            for (int e = 0; e < 4; e++) acc[i][j][e] = 0.f;                    \
    issue(0); issue(1); issue(2);                                              \
    const int a_r = lane & 15;                                                 \
    const int b_r = (lane & 7) + ((lane >> 3) & 1) * 8;                        \
    const int khl = (lane >> 4) * 8;                                           \
    for (int it = 0; it < niter; ++it) {                                       \
        const int rem = niter - 1 - it;                                        \
        if (rem >= 2)      asm volatile("cp.async.wait_group 2;\n" ::: "memory"); \
        else if (rem == 1) asm volatile("cp.async.wait_group 1;\n" ::: "memory"); \
        else               asm volatile("cp.async.wait_group 0;\n" ::: "memory"); \
        __syncthreads();                                                       \
        const uint32_t sb = sbase + (uint32_t)(it % FSTAGES) * FSTAGEB;        \
        _Pragma("unroll")                                                      \
        for (int kk = 0; kk < 64; kk += 16) {                                  \
            uint32_t a[2][4];                                                  \
            _Pragma("unroll")                                                  \
            for (int mb = 0; mb < 2; mb++) {                                   \
                uint32_t addr = sb + 2u * (uint32_t)((wm + mb * 16 + a_r) * FSTR + kk + khl); \
                ldsm4(a[mb][0], a[mb][1], a[mb][2], a[mb][3], addr);           \
            }                                                                  \
            uint32_t b[4][4];                                                  \
            _Pragma("unroll")                                                  \
            for (int nb = 0; nb < 4; nb++) {                                   \
                uint32_t addr = sb + FMATB +                                   \
                    2u * (uint32_t)((wn + nb * 16 + b_r) * FSTR + kk + khl);   \
                ldsm4(b[nb][0], b[nb][1], b[nb][2], b[nb][3], addr);           \
            }                                                                  \
            _Pragma("unroll")                                                  \
            for (int mb = 0; mb < 2; mb++) {                                   \
                _Pragma("unroll")                                              \
                for (int n8 = 0; n8 < 8; n8++) {                               \
                    const int nb = n8 >> 1, ww = n8 & 1;                       \
                    mma16816h(acc[mb][n8], a[mb], b[nb][ww], b[nb][ww + 2]);   \
                }                                                              \
            }                                                                  \
        }                                                                      \
        __syncthreads();                                                       \
        if (it + FSTAGES < niter) issue(it + FSTAGES);                         \
    }

// ---- fused QKV projection + RMSNorm + RoPE epilogue ----
// Virtual N = 6144 (Wq | Wk | Wv). Each 128-wide N block == one head's dims.
__global__ void __launch_bounds__(256, 2) gemm_qkv(
    const __half* __restrict__ A, int K,
    const float* __restrict__ cosp, const float* __restrict__ sinp,
    const float* __restrict__ qw,   const float* __restrict__ kw)
{
    extern __shared__ __half gs[];
    const uint32_t sbase = (uint32_t)__cvta_generic_to_shared(gs);
    const int tid  = threadIdx.x;
    const int lane = tid & 31, warp = tid >> 5;
    const int wm = (warp & 3) * 32;
    const int wn = (warp >> 2) * 64;
    const size_t bm = (size_t)blockIdx.y * 128;
    const int bn = blockIdx.x * 128;

    const __half* Bp; __half* Co; int ldc, col0, mode;
    if (bn < 4096)      { Bp = g_wq16 + (size_t)bn * K;          Co = g_q16; ldc = 4096; col0 = bn;        mode = 0; }
    else if (bn < 5120) { Bp = g_wk16 + (size_t)(bn - 4096) * K; Co = g_k16; ldc = 1024; col0 = bn - 4096; mode = 1; }
    else                { Bp = g_wv16 + (size_t)(bn - 5120) * K; Co = g_v16; ldc = 1024; col0 = bn - 5120; mode = 2; }

    GEMM_BODY(K)

    if (mode != 2) {
        // ---- fused RMSNorm + RoPE on fp32 accumulators ----
        float ssq[2][2];
        #pragma unroll
        for (int mb = 0; mb < 2; mb++) {
            float s0 = 0.f, s1 = 0.f;
            #pragma unroll
            for (int n8 = 0; n8 < 8; n8++) {
                s0 += acc[mb][n8][0] * acc[mb][n8][0] + acc[mb][n8][1] * acc[mb][n8][1];
                s1 += acc[mb][n8][2] * acc[mb][n8][2] + acc[mb][n8][3] * acc[mb][n8][3];
            }
            ssq[mb][0] = s0; ssq[mb][1] = s1;
        }
        #pragma unroll
        for (int mb = 0; mb < 2; mb++)
            #pragma unroll
            for (int h2 = 0; h2 < 2; h2++) {
                ssq[mb][h2] += __shfl_xor_sync(0xffffffffu, ssq[mb][h2], 1);
                ssq[mb][h2] += __shfl_xor_sync(0xffffffffu, ssq[mb][h2], 2);
            }
        // cross-warp (wn=0 vs wn=64 partials) via smem (mainloop smem retired)
        float* buf = (float*)gs;   // 256 floats
        if ((lane & 3) == 0) {
            #pragma unroll
            for (int mb = 0; mb < 2; mb++)
                #pragma unroll
                for (int h2 = 0; h2 < 2; h2++) {
                    int rloc = wm + mb * 16 + (lane >> 2) + h2 * 8;
                    buf[(warp >> 2) * 128 + rloc] = ssq[mb][h2];
                }
        }
        __syncthreads();
        float rs[2][2];
        #pragma unroll
        for (int mb = 0; mb < 2; mb++)
            #pragma unroll
            for (int h2 = 0; h2 < 2; h2++) {
                int rloc = wm + mb * 16 + (lane >> 2) + h2 * 8;
                float tot = buf[rloc] + buf[128 + rloc];
                rs[mb][h2] = rsqrtf(tot * (1.0f / HD) + RMS_EPS);
            }

        const float* w = (mode == 0) ? qw : kw;
        // normalize (x * rs * w[d])
        #pragma unroll
        for (int mb = 0; mb < 2; mb++) {
            #pragma unroll
            for (int n8 = 0; n8 < 8; n8++) {
                int cl = wn + n8 * 8 + (lane & 3) * 2;   // 0..127 within head
                float wc0 = w[cl], wc1 = w[cl + 1];
                acc[mb][n8][0] *= rs[mb][0] * wc0;
                acc[mb][n8][1] *= rs[mb][0] * wc1;
                acc[mb][n8][2] *= rs[mb][1] * wc0;
                acc[mb][n8][3] *= rs[mb][1] * wc1;
            }
        }
        // RoPE: only cols 0..63 (warps with wn==0); partner col = col ^ 32
        if (wn == 0) {
            #pragma unroll
            for (int mb = 0; mb < 2; mb++) {
                #pragma unroll
                for (int n8 = 0; n8 < 4; n8++) {
                    const int cl = n8 * 8 + (lane & 3) * 2;   // 0..30
                    const int ch = cl + 32;
                    #pragma unroll
                    for (int h2 = 0; h2 < 2; h2++) {
                        size_t tok = bm + wm + mb * 16 + (lane >> 2) + h2 * 8;
                        float c0 = cosp[tok * ROTD + cl],     s0 = sinp[tok * ROTD + cl];
                        float c1 = cosp[tok * ROTD + cl + 1], s1 = sinp[tok * ROTD + cl + 1];
                        float C0 = cosp[tok * ROTD + ch],     S0 = sinp[tok * ROTD + ch];
                        float C1 = cosp[tok * ROTD + ch + 1], S1 = sinp[tok * ROTD + ch + 1];
                        const int e0 = h2 * 2;
                        float alo0 = acc[mb][n8][e0],     alo1 = acc[mb][n8][e0 + 1];
                        float ahi0 = acc[mb][n8 + 4][e0], ahi1 = acc[mb][n8 + 4][e0 + 1];
                        acc[mb][n8][e0]         = alo0 * c0 - ahi0 * s0;
                        acc[mb][n8][e0 + 1]     = alo1 * c1 - ahi1 * s1;
                        acc[mb][n8 + 4][e0]     = ahi0 * C0 + alo0 * S0;
                        acc[mb][n8 + 4][e0 + 1] = ahi1 * C1 + alo1 * S1;
                    }
                }
            }
        }
        // Q pre-scale for log2-domain softmax
        if (mode == 0) {
            const float ps = ATT_SCALE * LOG2E;
            #pragma unroll
            for (int mb = 0; mb < 2; mb++)
                #pragma unroll
                for (int n8 = 0; n8 < 8; n8++)
                    #pragma unroll
                    for (int e = 0; e < 4; e++) acc[mb][n8][e] *= ps;
        }
    }

    #pragma unroll
    for (int mb = 0; mb < 2; mb++) {
        const size_t row = bm + wm + mb * 16 + (lane >> 2);
        #pragma unroll
        for (int n8 = 0; n8 < 8; n8++) {
            const size_t col = col0 + wn + n8 * 8 + (lane & 3) * 2;
            *(uint32_t*)&Co[row * ldc + col] =
                packh2(__float2half_rn(acc[mb][n8][0]), __float2half_rn(acc[mb][n8][1]));
            *(uint32_t*)&Co[(row + 8) * ldc + col] =
                packh2(__float2half_rn(acc[mb][n8][2]), __float2half_rn(acc[mb][n8][3]));
        }
    }
}

// ---- O projection: fp32 out ----
__global__ void __launch_bounds__(256, 2) gemm_gen(
    const __half* __restrict__ A, const __half* __restrict__ B,
    float* __restrict__ C, int N, int K)
{
    extern __shared__ __half gs[];
    const uint32_t sbase = (uint32_t)__cvta_generic_to_shared(gs);
    const int tid  = threadIdx.x;
    const int lane = tid & 31, warp = tid >> 5;
    const int wm = (warp & 3) * 32;
    const int wn = (warp >> 2) * 64;
    const size_t bm = (size_t)blockIdx.y * 128;
    const int bn = blockIdx.x * 128;
    const __half* Bp = B + (size_t)bn * K;

    GEMM_BODY(K)

    #pragma unroll
    for (int mb = 0; mb < 2; mb++) {
        const size_t row = bm + wm + mb * 16 + (lane >> 2);
        #pragma unroll
        for (int n8 = 0; n8 < 8; n8++) {
            const size_t col = bn + wn + n8 * 8 + (lane & 3) * 2;
            *(float2*)&C[row * N + col] = make_float2(acc[mb][n8][0], acc[mb][n8][1]);
            *(float2*)&C[(row + 8) * N + col] = make_float2(acc[mb][n8][2], acc[mb][n8][3]);
        }
    }
}

// ---------------------------------------------------------------------------
// fp16 tensor-core causal flash attention; log2-domain softmax.
// BM=128 (8 warps x 16 rows), BN=64, D=128, 256 threads, 2 CTAs/SM.
// ONE sync per iteration: after the sync all warps have completed iter j-1,
// so issuing load_kv(j+1) mid-iteration (overwriting buffer (j-1)&1) is
// race-free. Prefetch window = PV(j) duration (~1000cyc) > L2 load latency.
// ---------------------------------------------------------------------------
#define ASTR 136
#define QMAT (128 * ASTR)
#define AMAT (64 * ASTR)
#define ATT_SMEM ((QMAT + 4 * AMAT) * 2)   // 104448 B

__global__ void __launch_bounds__(256, 2) attn_mma_kernel()
{
    extern __shared__ __half sh[];
    const uint32_t sbase = (uint32_t)__cvta_generic_to_shared(sh);

    const int tid  = threadIdx.x;
    const int lane = tid & 31, w = tid >> 5;
    const int qtile = (S_LEN / 128 - 1) - blockIdx.x;
    const int h  = blockIdx.y;
    const int hk = h >> 2;
    const int q0 = qtile * 128;
    const int qrow0 = q0 + w * 16;
    const int jmax = 2 * qtile + 1;

    const int b_r = (lane & 7) + ((lane >> 3) & 1) * 8;
    const int khl = (lane >> 4) * 8;
    const int r   = lane >> 2;

    auto load_q = [&]() {
        #pragma unroll
        for (int i = 0; i < 8; i++) {
            int c   = tid + i * 256;
            int row = c >> 4, col = c & 15;
            const __half* src = g_q16 + ((size_t)(q0 + row) * NH + h) * HD + col * 8;
            uint32_t dst = sbase + (uint32_t)(row * ASTR) * 2 + col * 16;
            cp16(dst, src);
        }
    };
    auto load_kv = [&](int j) {
        const int kvb = QMAT + (j & 1) * 2 * AMAT;
        #pragma unroll
        for (int i = 0; i < 8; i++) {
            int c   = tid + i * 256;
            int mat = c >> 10;
            int rem = c & 1023;
            int row = rem >> 4, col = rem & 15;
            const __half* srcb = (mat == 0) ? g_k16 : g_v16;
            const __half* src = srcb + ((size_t)(j * 64 + row) * NKV + hk) * HD + col * 8;
            uint32_t dst = sbase + (uint32_t)(kvb + mat * AMAT + row * ASTR) * 2 + col * 16;
            cp16(dst, src);
        }
    };

    load_q();
    load_kv(0);
    asm volatile("cp.async.commit_group;\n" ::: "memory");

    float oacc[16][4];
    #pragma unroll
    for (int i = 0; i < 16; i++)
        #pragma unroll
        for (int e = 0; e < 4; e++) oacc[i][e] = 0.f;
    float m0 = -INFINITY, m1 = -INFINITY, l0 = 0.f, l1 = 0.f;

    for (int j = 0; j <= jmax; j++) {
        // wait for load(j): it was issued mid-iter j-1 (or prologue) and is
        // the only group in flight.
        asm volatile("cp.async.wait_group 0;\n" ::: "memory");
        // single barrier: (a) makes load(j) visible to all warps,
        // (b) guarantees every warp finished iter j-1 -> buffer (j+1)&1 free.
        __syncthreads();

        const bool active = (j * 64 <= qrow0 + 15);
        const int kvb = QMAT + (j & 1) * 2 * AMAT;
        float sacc[8][4];
        uint32_t ap[4][4];

        if (active) {
            // ---- S = Q K^T (log2 units; Q pre-scaled) ----
            #pragma unroll
            for (int b = 0; b < 8; b++)
                #pragma unroll
                for (int e = 0; e < 4; e++) sacc[b][e] = 0.f;

            #pragma unroll
            for (int k0 = 0; k0 < 8; k0++) {
                uint32_t qaddr = sbase +
                    (uint32_t)((w * 16 + (lane & 15)) * ASTR + k0 * 16 + 8 * (lane >> 4)) * 2;
                uint32_t aq[4];
                ldsm4(aq[0], aq[1], aq[2], aq[3], qaddr);
                #pragma unroll
                for (int nb = 0; nb < 4; nb++) {
                    uint32_t kaddr = sbase +
                        (uint32_t)(kvb + (nb * 16 + b_r) * ASTR + k0 * 16 + khl) * 2;
                    uint32_t kf[4];
                    ldsm4(kf[0], kf[1], kf[2], kf[3], kaddr);
                    mma16816h(sacc[2 * nb],     aq, kf[0], kf[2]);
                    mma16816h(sacc[2 * nb + 1], aq, kf[1], kf[3]);
                }
            }

            // ---- causal mask ----
            const bool full = (j * 64 + 63 <= qrow0);
            if (!full) {
                #pragma unroll
                for (int b = 0; b < 8; b++) {
                    int colb = j * 64 + b * 8 + 2 * (lane & 3);
                    int rlo = qrow0 + r, rhi = rlo + 8;
                    if (colb     > rlo) sacc[b][0] = -1e30f;
                    if (colb + 1 > rlo) sacc[b][1] = -1e30f;
                    if (colb     > rhi) sacc[b][2] = -1e30f;
                    if (colb + 1 > rhi) sacc[b][3] = -1e30f;
                }
            }

            // ---- online softmax (log2 domain) ----
            float mx0 = -INFINITY, mx1 = -INFINITY;
            #pragma unroll
            for (int b = 0; b < 8; b++) {
                mx0 = fmaxf(mx0, fmaxf(sacc[b][0], sacc[b][1]));
                mx1 = fmaxf(mx1, fmaxf(sacc[b][2], sacc[b][3]));
            }
            mx0 = fmaxf(mx0, __shfl_xor_sync(0xffffffffu, mx0, 1));
            mx0 = fmaxf(mx0, __shfl_xor_sync(0xffffffffu, mx0, 2));
            mx1 = fmaxf(mx1, __shfl_xor_sync(0xffffffffu, mx1, 1));
            mx1 = fmaxf(mx1, __shfl_xor_sync(0xffffffffu, mx1, 2));
            float mn0 = fmaxf(m0, mx0), mn1 = fmaxf(m1, mx1);
            float f0 = exp2f(m0 - mn0), f1 = exp2f(m1 - mn1);
            m0 = mn0; m1 = mn1;

            float s0 = 0.f, s1 = 0.f;
            #pragma unroll
            for (int b = 0; b < 8; b++) {
                sacc[b][0] = exp2f(sacc[b][0] - mn0);
                sacc[b][1] = exp2f(sacc[b][1] - mn0);
                sacc[b][2] = exp2f(sacc[b][2] - mn1);
                sacc[b][3] = exp2f(sacc[b][3] - mn1);
                s0 += sacc[b][0] + sacc[b][1];
                s1 += sacc[b][2] + sacc[b][3];
            }
            s0 += __shfl_xor_sync(0xffffffffu, s0, 1);
            s0 += __shfl_xor_sync(0xffffffffu, s0, 2);
            s1 += __shfl_xor_sync(0xffffffffu, s1, 1);
            s1 += __shfl_xor_sync(0xffffffffu, s1, 2);
            l0 = l0 * f0 + s0;
            l1 = l1 * f1 + s1;

            #pragma unroll
            for (int nb = 0; nb < 16; nb++) {
                oacc[nb][0] *= f0; oacc[nb][1] *= f0;
                oacc[nb][2] *= f1; oacc[nb][3] *= f1;
            }

            // ---- pack P into fp16 A-fragments ----
            #pragma unroll
            for (int t = 0; t < 4; t++) {
                #pragma unroll
                for (int q = 0; q < 4; q++) {
                    const int blk = 2 * t + (q >> 1);
                    const int e0  = (q & 1) * 2;
                    ap[t][q] = packh2(__float2half_rn(sacc[blk][e0]),
                                      __float2half_rn(sacc[blk][e0 + 1]));
                }
            }
        }

        // ---- issue load(j+1) mid-iteration: overlaps with PV(j) ----
        if (j + 1 <= jmax) {
            load_kv(j + 1);
            asm volatile("cp.async.commit_group;\n" ::: "memory");
        }

        // ---- O += P V ----
        if (active) {
            #pragma unroll
            for (int t = 0; t < 4; t++) {
                #pragma unroll
                for (int nb = 0; nb < 8; nb++) {
                    uint32_t vaddr = sbase +
                        (uint32_t)(kvb + AMAT +
                                   (t * 16 + (lane & 15)) * ASTR + nb * 16 + 8 * (lane >> 4)) * 2;
                    uint32_t vf[4];
                    ldsm4t(vf[0], vf[1], vf[2], vf[3], vaddr);
                    mma16816h(oacc[2 * nb],     ap[t], vf[0], vf[1]);
                    mma16816h(oacc[2 * nb + 1], ap[t], vf[2], vf[3]);
                }
            }
        }
    }

    const float inv0 = 1.f / l0, inv1 = 1.f / l1;
    #pragma unroll
    for (int nb = 0; nb < 16; nb++) {
        const int col = nb * 8 + 2 * (lane & 3);
        size_t i0 = ((size_t)(qrow0 + r) * NH + h) * HD + col;
        size_t i1 = ((size_t)(qrow0 + r + 8) * NH + h) * HD + col;
        *(uint32_t*)(g_ao16 + i0) = packh2(
            __float2half_rn(oacc[nb][0] * inv0), __float2half_rn(oacc[nb][1] * inv0));
        *(uint32_t*)(g_ao16 + i1) = packh2(
            __float2half_rn(oacc[nb][2] * inv1), __float2half_rn(oacc[nb][3] * inv1));
    }
}

// ---------------------------------------------------------------------------
// kernel_launch
// ---------------------------------------------------------------------------
extern "C" void kernel_launch(void* const* d_in, const int* in_sizes, int n_in,
                              void* d_out, int out_size)
{
    const float* hidden = (const float*)d_in[0];
    const float* cosp   = (const float*)d_in[1];
    const float* sinp   = (const float*)d_in[2];
    const float* Wq     = (const float*)d_in[3];
    const float* Wk     = (const float*)d_in[4];
    const float* Wv     = (const float*)d_in[5];
    const float* Wo     = (const float*)d_in[6];
    const float* qw     = (const float*)d_in[7];
    const float* kw     = (const float*)d_in[8];
    float* out = (float*)d_out;

    __half *hid16, *wo16, *ao16;
    cudaGetSymbolAddress((void**)&hid16, g_hid16);
    cudaGetSymbolAddress((void**)&wo16,  g_wo16);
    cudaGetSymbolAddress((void**)&ao16,  g_ao16);

    // all fp32 -> fp16 conversions, one launch
    cvt_all<<<24576, 256>>>(hidden, Wq, Wk, Wv, Wo);

    cudaFuncSetAttribute(gemm_qkv, cudaFuncAttributeMaxDynamicSharedMemorySize, FSMEM);
    cudaFuncSetAttribute(gemm_gen, cudaFuncAttributeMaxDynamicSharedMemorySize, FSMEM);

    // fused QKV projection + RMSNorm + RoPE (virtual N = 6144), fp16 out
    gemm_qkv<<<dim3(48, S_LEN / 128), 256, FSMEM>>>(hid16, HID, cosp, sinp, qw, kw);

    // fp16 causal flash attention (single-sync pipelined)
    cudaFuncSetAttribute(attn_mma_kernel, cudaFuncAttributeMaxDynamicSharedMemorySize, ATT_SMEM);
    attn_mma_kernel<<<dim3(S_LEN / 128, NH), 256, ATT_SMEM>>>();

    // O projection -> d_out
    gemm_gen<<<dim3(HID / 128, S_LEN / 128), 256, FSMEM>>>(
        ao16, wo16, out, HID, NH * HD);
}